// round 1
// baseline (speedup 1.0000x reference)
#include <cuda_runtime.h>
#include <cstdint>

#define DFI __device__ __forceinline__

DFI float fsig(float x)  { return __fdividef(1.f, 1.f + __expf(-x)); }
DFI float ftanh(float x) { float e = __expf(2.f * x); return 1.f - __fdividef(2.f, e + 1.f); }
DFI float lrelu(float x) { return x > 0.f ? x : 0.01f * x; }

// ---------------- scratch (no dynamic allocation allowed) ----------------
__device__ float g_hlast[10240 * 64];
__device__ float g_ssrc[10240];
__device__ float g_sdst[10240];
__device__ float g_hatt[10240 * 64];
__device__ float g_hfc[10240 * 64];
__device__ float g_z[512 * 20 * 64];
__device__ float g_r[512 * 20 * 64];

// =========================================================================
// Fused 2-layer GRU. One warp owns 4 sequences; h kept in warp-private SMEM
// rows; both layers advanced per timestep (layer1 consumes layer0's h0_t).
// Weights transposed in SMEM: Wt[k*192 + o], lane touches o = lane + 32*j
// -> bank == lane, conflict-free. Lane owns hidden units {lane, lane+32}:
// its 6 outputs are exactly r,z,n for those two units.
// =========================================================================
template <int DIN, bool STORE_ALL>
__global__ void __launch_bounds__(640, 1) gru2_kernel(
    const float* __restrict__ X,
    const float* __restrict__ Wih0, const float* __restrict__ Whh0,
    const float* __restrict__ bih0, const float* __restrict__ bhh0,
    const float* __restrict__ Wih1, const float* __restrict__ Whh1,
    const float* __restrict__ bih1, const float* __restrict__ bhh1,
    float* __restrict__ OUT, int N, int T)
{
    extern __shared__ float sm[];
    const int WARPS = blockDim.x >> 5;
    const int SPB = WARPS * 4;                 // sequences per block
    float* wih0t = sm;                         // DIN*192
    float* whh0t = wih0t + DIN * 192;          // 64*192
    float* wih1t = whh0t + 64 * 192;           // 64*192
    float* whh1t = wih1t + 64 * 192;           // 64*192
    float* sb    = whh1t + 64 * 192;           // 4*192 biases
    float* sh0   = sb + 4 * 192;               // SPB*64
    float* sh1   = sh0 + SPB * 64;             // SPB*64
    float* sx    = sh1 + SPB * 64;             // WARPS*4*DIN

    const int tid = threadIdx.x, nth = blockDim.x;
    for (int i = tid; i < DIN * 192; i += nth) { int k = i / 192, o = i - k * 192; wih0t[i] = Wih0[o * DIN + k]; }
    for (int i = tid; i < 64 * 192; i += nth) {
        int k = i / 192, o = i - k * 192;
        whh0t[i] = Whh0[o * 64 + k];
        wih1t[i] = Wih1[o * 64 + k];
        whh1t[i] = Whh1[o * 64 + k];
    }
    for (int i = tid; i < 192; i += nth) { sb[i] = bih0[i]; sb[192 + i] = bhh0[i]; sb[384 + i] = bih1[i]; sb[576 + i] = bhh1[i]; }
    for (int i = tid; i < SPB * 64; i += nth) { sh0[i] = 0.f; sh1[i] = 0.f; }
    __syncthreads();

    const int w = tid >> 5, lane = tid & 31;
    const int sl = w * 4;                                     // local seq base
    const int sg = blockIdx.x * SPB + sl;                     // global seq base
    if (sg >= N) return;                                      // whole-warp guard

    int o_[6];
#pragma unroll
    for (int j = 0; j < 6; j++) o_[j] = ((j >> 1) << 6) + lane + ((j & 1) << 5);

    float* sxw = sx + w * 4 * DIN;
    const float* Xb = X + (long long)sg * T * DIN;

    for (int t = 0; t < T; ++t) {
        // stage x_t for the warp's 4 sequences
        for (int i = lane; i < 4 * DIN; i += 32) {
            int s = i / DIN, d = i - s * DIN;
            sxw[i] = Xb[(long long)s * T * DIN + t * DIN + d];
        }
        __syncwarp();

        // ---------------- layer 0 ----------------
        float ax[4][6], ah[4][6];
#pragma unroll
        for (int s = 0; s < 4; s++)
#pragma unroll
            for (int j = 0; j < 6; j++) { ax[s][j] = sb[o_[j]]; ah[s][j] = sb[192 + o_[j]]; }

#pragma unroll
        for (int d = 0; d < (DIN < 8 ? DIN : 0); d++) { // fully unroll tiny DIN
            float wv[6];
#pragma unroll
            for (int j = 0; j < 6; j++) wv[j] = wih0t[d * 192 + o_[j]];
#pragma unroll
            for (int s = 0; s < 4; s++) {
                float xv = sxw[s * DIN + d];
#pragma unroll
                for (int j = 0; j < 6; j++) ax[s][j] = fmaf(wv[j], xv, ax[s][j]);
            }
        }
        if (DIN >= 8) {
#pragma unroll 4
            for (int d = 0; d < DIN; d++) {
                float wv[6];
#pragma unroll
                for (int j = 0; j < 6; j++) wv[j] = wih0t[d * 192 + o_[j]];
#pragma unroll
                for (int s = 0; s < 4; s++) {
                    float xv = sxw[s * DIN + d];
#pragma unroll
                    for (int j = 0; j < 6; j++) ax[s][j] = fmaf(wv[j], xv, ax[s][j]);
                }
            }
        }
#pragma unroll 4
        for (int k = 0; k < 64; k++) {
            float wv[6];
#pragma unroll
            for (int j = 0; j < 6; j++) wv[j] = whh0t[k * 192 + o_[j]];
#pragma unroll
            for (int s = 0; s < 4; s++) {
                float hv = sh0[(sl + s) * 64 + k];
#pragma unroll
                for (int j = 0; j < 6; j++) ah[s][j] = fmaf(wv[j], hv, ah[s][j]);
            }
        }
        __syncwarp();
#pragma unroll
        for (int s = 0; s < 4; s++)
#pragma unroll
            for (int u = 0; u < 2; u++) {
                float r = fsig(ax[s][u] + ah[s][u]);
                float z = fsig(ax[s][2 + u] + ah[s][2 + u]);
                float n = ftanh(fmaf(r, ah[s][4 + u], ax[s][4 + u]));
                int hi = (sl + s) * 64 + lane + (u << 5);
                float hold = sh0[hi];
                sh0[hi] = (1.f - z) * n + z * hold;
            }
        __syncwarp();

        // ---------------- layer 1 (input = layer0's new h0) ----------------
#pragma unroll
        for (int s = 0; s < 4; s++)
#pragma unroll
            for (int j = 0; j < 6; j++) { ax[s][j] = sb[384 + o_[j]]; ah[s][j] = sb[576 + o_[j]]; }
#pragma unroll 2
        for (int k = 0; k < 64; k++) {
            float wx[6], wh[6];
#pragma unroll
            for (int j = 0; j < 6; j++) { wx[j] = wih1t[k * 192 + o_[j]]; wh[j] = whh1t[k * 192 + o_[j]]; }
#pragma unroll
            for (int s = 0; s < 4; s++) {
                float x0 = sh0[(sl + s) * 64 + k];
                float h1 = sh1[(sl + s) * 64 + k];
#pragma unroll
                for (int j = 0; j < 6; j++) { ax[s][j] = fmaf(wx[j], x0, ax[s][j]); ah[s][j] = fmaf(wh[j], h1, ah[s][j]); }
            }
        }
        __syncwarp();
#pragma unroll
        for (int s = 0; s < 4; s++)
#pragma unroll
            for (int u = 0; u < 2; u++) {
                float r = fsig(ax[s][u] + ah[s][u]);
                float z = fsig(ax[s][2 + u] + ah[s][2 + u]);
                float n = ftanh(fmaf(r, ah[s][4 + u], ax[s][4 + u]));
                int hi = (sl + s) * 64 + lane + (u << 5);
                float hold = sh1[hi];
                float hnew = (1.f - z) * n + z * hold;
                sh1[hi] = hnew;
                if (STORE_ALL) OUT[((long long)(sg + s) * T + t) * 64 + lane + (u << 5)] = hnew;
            }
        __syncwarp();
    }
    if (!STORE_ALL) {
#pragma unroll
        for (int s = 0; s < 4; s++)
#pragma unroll
            for (int u = 0; u < 2; u++)
                OUT[(long long)(sg + s) * 64 + lane + (u << 5)] = sh1[(sl + s) * 64 + lane + (u << 5)];
    }
}

// =========================================================================
// xp = h @ trans_W.T + trans_b ; s_dst = xp @ a[:64] ; s_src = xp @ a[64:]
// =========================================================================
__global__ void trans_score_kernel(const float* __restrict__ H,
    const float* __restrict__ W, const float* __restrict__ b,
    const float* __restrict__ a, float* __restrict__ ssrc,
    float* __restrict__ sdst, int Nrows)
{
    __shared__ float sW[4096], sbv[64], sad[64], sas[64];
    for (int i = threadIdx.x; i < 4096; i += blockDim.x) sW[i] = W[i];
    for (int i = threadIdx.x; i < 64; i += blockDim.x) { sbv[i] = b[i]; sad[i] = a[i]; sas[i] = a[64 + i]; }
    __syncthreads();
    for (int row = blockIdx.x * blockDim.x + threadIdx.x; row < Nrows; row += gridDim.x * blockDim.x) {
        float h[64];
        const float4* hp = (const float4*)(H + (long long)row * 64);
#pragma unroll
        for (int q = 0; q < 16; q++) { float4 v = hp[q]; h[4*q] = v.x; h[4*q+1] = v.y; h[4*q+2] = v.z; h[4*q+3] = v.w; }
        float sd = 0.f, ss = 0.f;
#pragma unroll 4
        for (int o = 0; o < 64; o++) {
            float acc = sbv[o];
#pragma unroll
            for (int k = 0; k < 64; k++) acc = fmaf(h[k], sW[o * 64 + k], acc);
            sd = fmaf(acc, sad[o], sd);
            ss = fmaf(acc, sas[o], ss);
        }
        sdst[row] = sd; ssrc[row] = ss;
    }
}

// =========================================================================
// Dense per-group GAT: out[i] = softmax_j(lrelu(ssrc[i]+sdst[j])) @ h + h[i]
// grid = 20 groups x 8 chunks, 8 warps/block, 8 rows/warp.
// =========================================================================
__global__ void gat_att_kernel(const float* __restrict__ Hin,
    const float* __restrict__ ssrc, const float* __restrict__ sdst,
    float* __restrict__ Hout)
{
    __shared__ float sd[512];
    __shared__ float se[8][512];
    const int g = blockIdx.x >> 3, chunk = blockIdx.x & 7;
    for (int i = threadIdx.x; i < 512; i += blockDim.x) sd[i] = sdst[g * 512 + i];
    __syncthreads();
    const int w = threadIdx.x >> 5, lane = threadIdx.x & 31;
    const float* Hg = Hin + (long long)g * 512 * 64;
    for (int rr = 0; rr < 8; ++rr) {
        const int i = chunk * 64 + w * 8 + rr;
        const float si = ssrc[g * 512 + i];
        float m = -1e30f, sc[16];
#pragma unroll
        for (int jj = 0; jj < 16; jj++) {
            float v = lrelu(si + sd[lane + (jj << 5)]);
            sc[jj] = v; m = fmaxf(m, v);
        }
#pragma unroll
        for (int off = 16; off; off >>= 1) m = fmaxf(m, __shfl_xor_sync(~0u, m, off));
        float ssum = 0.f;
#pragma unroll
        for (int jj = 0; jj < 16; jj++) {
            float e = __expf(sc[jj] - m);
            se[w][lane + (jj << 5)] = e; ssum += e;
        }
#pragma unroll
        for (int off = 16; off; off >>= 1) ssum += __shfl_xor_sync(~0u, ssum, off);
        __syncwarp();
        float2 acc = make_float2(0.f, 0.f);
        const int c = lane << 1;
#pragma unroll 4
        for (int j = 0; j < 512; j++) {
            float e = se[w][j];
            float2 hv = *(const float2*)(Hg + j * 64 + c);
            acc.x = fmaf(e, hv.x, acc.x);
            acc.y = fmaf(e, hv.y, acc.y);
        }
        float inv = __fdividef(1.f, ssum);
        float2 hi = *(const float2*)(Hg + i * 64 + c);
        float2 res; res.x = fmaf(acc.x, inv, hi.x); res.y = fmaf(acc.y, inv, hi.y);
        *(float2*)(Hout + ((long long)g * 512 + i) * 64 + c) = res;
        __syncwarp();
    }
}

// ============================ fc: 64x64 linear ===========================
__global__ void fc_kernel(const float* __restrict__ IN, const float* __restrict__ W,
                          const float* __restrict__ b, float* __restrict__ O, int Nrows)
{
    __shared__ float sW[4096], sb2[64];
    for (int i = threadIdx.x; i < 4096; i += blockDim.x) sW[i] = W[i];
    for (int i = threadIdx.x; i < 64; i += blockDim.x) sb2[i] = b[i];
    __syncthreads();
    for (int row = blockIdx.x * blockDim.x + threadIdx.x; row < Nrows; row += gridDim.x * blockDim.x) {
        float h[64];
        const float4* hp = (const float4*)(IN + (long long)row * 64);
#pragma unroll
        for (int q = 0; q < 16; q++) { float4 v = hp[q]; h[4*q] = v.x; h[4*q+1] = v.y; h[4*q+2] = v.z; h[4*q+3] = v.w; }
        float* op = O + (long long)row * 64;
#pragma unroll 2
        for (int o = 0; o < 64; o++) {
            float acc = sb2[o];
#pragma unroll
            for (int k = 0; k < 64; k++) acc = fmaf(h[k], sW[o * 64 + k], acc);
            op[o] = acc;
        }
    }
}

// ============= z = tanh(permute(hfc) @ al_in_W.T + al_in_b) ==============
// output row r = i*20+k  reads hfc row (k*512+i)
__global__ void z_kernel(const float* __restrict__ Hfc, const float* __restrict__ W,
                         const float* __restrict__ b, float* __restrict__ Z)
{
    __shared__ float sW[4096], sb2[64];
    for (int i = threadIdx.x; i < 4096; i += blockDim.x) sW[i] = W[i];
    for (int i = threadIdx.x; i < 64; i += blockDim.x) sb2[i] = b[i];
    __syncthreads();
    int r = blockIdx.x * blockDim.x + threadIdx.x;
    if (r >= 512 * 20) return;
    int i = r / 20, k = r - i * 20;
    const float* hp = Hfc + (long long)(k * 512 + i) * 64;
    float h[64];
#pragma unroll
    for (int q = 0; q < 16; q++) { float4 v = ((const float4*)hp)[q]; h[4*q] = v.x; h[4*q+1] = v.y; h[4*q+2] = v.z; h[4*q+3] = v.w; }
    float* op = Z + (long long)r * 64;
#pragma unroll 2
    for (int o = 0; o < 64; o++) {
        float acc = sb2[o];
#pragma unroll
        for (int kk = 0; kk < 64; kk++) acc = fmaf(h[kk], sW[o * 64 + kk], acc);
        op[o] = ftanh(acc);
    }
}

// ======================= ALSTM attention head ============================
__global__ void alstm_head_kernel(const float* __restrict__ R,
    const float* __restrict__ W1, const float* __restrict__ b1,
    const float* __restrict__ W2, const float* __restrict__ Wout,
    const float* __restrict__ bout, float* __restrict__ outv)
{
    __shared__ float sW1t[64 * 32], sb1[32], sW2[32], sWo[128];
    __shared__ float sr[8][64], ssk[8][20];
    for (int i = threadIdx.x; i < 2048; i += blockDim.x) { int d = i >> 5, o = i & 31; sW1t[i] = W1[o * 64 + d]; }
    if (threadIdx.x < 32) { sb1[threadIdx.x] = b1[threadIdx.x]; sW2[threadIdx.x] = W2[threadIdx.x]; }
    for (int i = threadIdx.x; i < 128; i += blockDim.x) sWo[i] = Wout[i];
    __syncthreads();
    const int w = threadIdx.x >> 5, lane = threadIdx.x & 31;
    const int i = blockIdx.x * 8 + w;
    const float* Ri = R + (long long)i * 20 * 64;
    for (int k = 0; k < 20; k++) {
        sr[w][lane] = Ri[k * 64 + lane];
        sr[w][lane + 32] = Ri[k * 64 + lane + 32];
        __syncwarp();
        float acc = sb1[lane];
#pragma unroll
        for (int d = 0; d < 64; d++) acc = fmaf(sr[w][d], sW1t[(d << 5) + lane], acc);
        float p = ftanh(acc) * sW2[lane];
#pragma unroll
        for (int off = 16; off; off >>= 1) p += __shfl_xor_sync(~0u, p, off);
        if (lane == 0) ssk[w][k] = p;
        __syncwarp();
    }
    float m = -1e30f;
    for (int k = 0; k < 20; k++) m = fmaxf(m, ssk[w][k]);
    float ssum = 0.f;
    for (int k = 0; k < 20; k++) ssum += __expf(ssk[w][k] - m);
    float inv = __fdividef(1.f, ssum);
    float accf = 0.f;
    for (int k = 0; k < 20; k++) {
        float ak = __expf(ssk[w][k] - m) * inv;
        float r1 = Ri[k * 64 + lane], r2 = Ri[k * 64 + lane + 32];
        accf = fmaf(ak * r1, sWo[64 + lane], accf);
        accf = fmaf(ak * r2, sWo[96 + lane], accf);
    }
    {
        float r1 = Ri[19 * 64 + lane], r2 = Ri[19 * 64 + lane + 32];
        accf = fmaf(r1, sWo[lane], accf);
        accf = fmaf(r2, sWo[32 + lane], accf);
    }
#pragma unroll
    for (int off = 16; off; off >>= 1) accf += __shfl_xor_sync(~0u, accf, off);
    if (lane == 0) outv[i] = accf + bout[0];
}

// ============ pred = lrelu(hfc[group 19]) @ fco_W.T + fco_b ==============
__global__ void pred_kernel(const float* __restrict__ Hfc, const float* __restrict__ fcoW,
                            const float* __restrict__ fcob, float* __restrict__ outv)
{
    __shared__ float sw[64];
    if (threadIdx.x < 64) sw[threadIdx.x] = fcoW[threadIdx.x];
    __syncthreads();
    int i = blockIdx.x * blockDim.x + threadIdx.x;
    if (i < 512) {
        const float* hp = Hfc + (long long)(19 * 512 + i) * 64;
        float s = fcob[0];
#pragma unroll 8
        for (int c = 0; c < 64; c++) { float v = hp[c]; v = v > 0.f ? v : 0.01f * v; s = fmaf(v, sw[c], s); }
        outv[512 + i] = s;
    }
}

// =========================================================================
extern "C" void kernel_launch(void* const* d_in, const int* in_sizes, int n_in,
                              void* d_out, int out_size)
{
    const float* x        = (const float*)d_in[0];
    const float* rWih0    = (const float*)d_in[1];
    const float* rWhh0    = (const float*)d_in[2];
    const float* rbih0    = (const float*)d_in[3];
    const float* rbhh0    = (const float*)d_in[4];
    const float* rWih1    = (const float*)d_in[5];
    const float* rWhh1    = (const float*)d_in[6];
    const float* rbih1    = (const float*)d_in[7];
    const float* rbhh1    = (const float*)d_in[8];
    const float* trans_W  = (const float*)d_in[9];
    const float* trans_b  = (const float*)d_in[10];
    const float* a_vec    = (const float*)d_in[11];
    const float* fc_W     = (const float*)d_in[12];
    const float* fc_b     = (const float*)d_in[13];
    const float* fco_W    = (const float*)d_in[14];
    const float* fco_b    = (const float*)d_in[15];
    const float* al_in_W  = (const float*)d_in[16];
    const float* al_in_b  = (const float*)d_in[17];
    const float* aWih0    = (const float*)d_in[18];
    const float* aWhh0    = (const float*)d_in[19];
    const float* abih0    = (const float*)d_in[20];
    const float* abhh0    = (const float*)d_in[21];
    const float* aWih1    = (const float*)d_in[22];
    const float* aWhh1    = (const float*)d_in[23];
    const float* abih1    = (const float*)d_in[24];
    const float* abhh1    = (const float*)d_in[25];
    const float* att1_W   = (const float*)d_in[26];
    const float* att1_b   = (const float*)d_in[27];
    const float* att2_W   = (const float*)d_in[28];
    const float* out_W    = (const float*)d_in[29];
    const float* out_b    = (const float*)d_in[30];
    float* out = (float*)d_out;

    float *hlast, *ssrc, *sdst, *hatt, *hfc, *zb, *rb;
    cudaGetSymbolAddress((void**)&hlast, g_hlast);
    cudaGetSymbolAddress((void**)&ssrc,  g_ssrc);
    cudaGetSymbolAddress((void**)&sdst,  g_sdst);
    cudaGetSymbolAddress((void**)&hatt,  g_hatt);
    cudaGetSymbolAddress((void**)&hfc,   g_hfc);
    cudaGetSymbolAddress((void**)&zb,    g_z);
    cudaGetSymbolAddress((void**)&rb,    g_r);

    // dynamic smem: DIN*192 + 3*64*192 + 4*192 + 2*SPB*64 + WARPS*4*DIN floats
    const int ENC_SMEM = (6 * 192 + 3 * 64 * 192 + 4 * 192 + 2 * 80 * 64 + 20 * 4 * 6) * 4;   // 198016
    const int AL_SMEM  = (64 * 192 + 3 * 64 * 192 + 4 * 192 + 2 * 16 * 64 + 4 * 4 * 64) * 4;  // 211968
    cudaFuncSetAttribute((const void*)gru2_kernel<6, false>,
                         cudaFuncAttributeMaxDynamicSharedMemorySize, ENC_SMEM);
    cudaFuncSetAttribute((const void*)gru2_kernel<64, true>,
                         cudaFuncAttributeMaxDynamicSharedMemorySize, AL_SMEM);

    // 1) encoder: 2-layer GRU, N=10240, T=60 -> hlast (128 blocks = 1 wave)
    gru2_kernel<6, false><<<128, 640, ENC_SMEM>>>(
        x, rWih0, rWhh0, rbih0, rbhh0, rWih1, rWhh1, rbih1, rbhh1, hlast, 10240, 60);

    // 2) trans projection + rank-1 scores
    trans_score_kernel<<<40, 256>>>(hlast, trans_W, trans_b, a_vec, ssrc, sdst, 10240);

    // 3) per-group dense attention + residual
    gat_att_kernel<<<160, 256>>>(hlast, ssrc, sdst, hatt);

    // 4) fc
    fc_kernel<<<40, 256>>>(hatt, fc_W, fc_b, hfc, 10240);

    // 5) z = tanh(permuted hfc @ al_in_W.T + b)
    z_kernel<<<40, 256>>>(hfc, al_in_W, al_in_b, zb);

    // 6) ALSTM 2-layer GRU over K=20, batch 512, store all timesteps
    gru2_kernel<64, true><<<32, 128, AL_SMEM>>>(
        zb, aWih0, aWhh0, abih0, abhh0, aWih1, aWhh1, abih1, abhh1, rb, 512, 20);

    // 7) ALSTM attention head -> alstm_out (out[0:512])
    alstm_head_kernel<<<64, 256>>>(rb, att1_W, att1_b, att2_W, out_W, out_b, out);

    // 8) pred head -> out[512:1024]
    pred_kernel<<<2, 256>>>(hfc, fco_W, fco_b, out);
}

// round 3
// speedup vs baseline: 1.0276x; 1.0276x over previous
#include <cuda_runtime.h>
#include <cstdint>

#define DFI __device__ __forceinline__
typedef unsigned long long u64;

DFI float fsig(float x)  { return __fdividef(1.f, 1.f + __expf(-x)); }
DFI float ftanh(float x) { float e = __expf(2.f * x); return 1.f - __fdividef(2.f, e + 1.f); }
DFI float lrelu(float x) { return x > 0.f ? x : 0.01f * x; }

DFI u64 lds64(const float* p) { return *reinterpret_cast<const u64*>(p); }
DFI u64 pk0(float lo) { u64 r; asm("mov.b64 %0,{%1,%2};" : "=l"(r) : "f"(lo), "f"(0.f)); return r; }
DFI float red2(u64 v) { float lo, hi; asm("mov.b64 {%0,%1},%2;" : "=f"(lo), "=f"(hi) : "l"(v)); return lo + hi; }
DFI u64 ffma2(u64 a, u64 b, u64 c) { u64 d; asm("fma.rn.f32x2 %0,%1,%2,%3;" : "=l"(d) : "l"(a), "l"(b), "l"(c)); return d; }

// ---------------- scratch (no dynamic allocation allowed) ----------------
__device__ float g_hlast[10240 * 64];
__device__ float g_ssrc[10240];
__device__ float g_sdst[10240];
__device__ float g_hatt[10240 * 64];
__device__ float g_hfc[10240 * 64];
__device__ float g_z[512 * 20 * 64];
__device__ float g_r[512 * 20 * 64];

// =========================================================================
// Fused 2-layer GRU, f32x2-packed over k-pairs (FFMA2).
// One warp owns 4 sequences; h in warp-private SMEM rows (contiguous k, so
// LDS.64 loads (h[2k],h[2k+1])). Weights pre-packed in SMEM as float2 over
// k-pairs: wp[k2*192+o] = {W[o][2k2], W[o][2k2+1]}; lane touches o=lane+32j
// -> 8B lane stride, conflict-free. r/z gates accumulate Wih-part and
// Whh-part into ONE accumulator (biases pre-summed); n keeps xn/hn separate.
// =========================================================================
template <int DIN, bool STORE_ALL>
__global__ void __launch_bounds__(576, 1) gru2p_kernel(
    const float* __restrict__ X,
    const float* __restrict__ Wih0, const float* __restrict__ Whh0,
    const float* __restrict__ bih0, const float* __restrict__ bhh0,
    const float* __restrict__ Wih1, const float* __restrict__ Whh1,
    const float* __restrict__ bih1, const float* __restrict__ bhh1,
    float* __restrict__ OUT, int N, int T)
{
    extern __shared__ float sm[];
    const int WARPS = blockDim.x >> 5;
    const int SPB = WARPS * 4;
    float* wih0p = sm;                          // DIN*192 floats ((DIN/2)*192 float2)
    float* whh0p = wih0p + DIN * 192;           // 12288
    float* wih1p = whh0p + 32 * 384;            // 12288
    float* whh1p = wih1p + 32 * 384;            // 12288
    float* sb    = whh1p + 32 * 384;            // 512
    float* sh0   = sb + 512;                    // SPB*64
    float* sh1   = sh0 + SPB * 64;              // SPB*64
    float* sx    = sh1 + SPB * 64;              // WARPS*4*DIN

    const int tid = threadIdx.x, nth = blockDim.x;
    for (int i = tid; i < (DIN / 2) * 192; i += nth) {
        int k2 = i / 192, o = i - k2 * 192;
        wih0p[2 * i]     = Wih0[o * DIN + 2 * k2];
        wih0p[2 * i + 1] = Wih0[o * DIN + 2 * k2 + 1];
    }
    for (int i = tid; i < 32 * 192; i += nth) {
        int k2 = i / 192, o = i - k2 * 192;
        whh0p[2 * i] = Whh0[o * 64 + 2 * k2]; whh0p[2 * i + 1] = Whh0[o * 64 + 2 * k2 + 1];
        wih1p[2 * i] = Wih1[o * 64 + 2 * k2]; wih1p[2 * i + 1] = Wih1[o * 64 + 2 * k2 + 1];
        whh1p[2 * i] = Whh1[o * 64 + 2 * k2]; whh1p[2 * i + 1] = Whh1[o * 64 + 2 * k2 + 1];
    }
    for (int i = tid; i < 128; i += nth) { sb[i] = bih0[i] + bhh0[i]; sb[256 + i] = bih1[i] + bhh1[i]; }
    for (int i = tid; i < 64; i += nth) {
        sb[128 + i] = bih0[128 + i]; sb[192 + i] = bhh0[128 + i];
        sb[384 + i] = bih1[128 + i]; sb[448 + i] = bhh1[128 + i];
    }
    for (int i = tid; i < SPB * 64; i += nth) { sh0[i] = 0.f; sh1[i] = 0.f; }
    __syncthreads();

    const int w = tid >> 5, lane = tid & 31;
    const int sl = w * 4;
    const int sg = blockIdx.x * SPB + sl;
    if (sg >= N) return;

    int wo[6];
#pragma unroll
    for (int j = 0; j < 6; j++) wo[j] = 2 * (((j >> 1) << 6) + lane + ((j & 1) << 5));

    float* sxw = sx + w * 4 * DIN;
    const float* Xb = X + (long long)sg * T * DIN;

    for (int t = 0; t < T; ++t) {
        // stage x_t for the warp's 4 sequences
        for (int i = lane; i < 4 * DIN; i += 32) {
            int s = i / DIN, d = i - s * DIN;
            sxw[i] = Xb[(long long)s * T * DIN + t * DIN + d];
        }
        __syncwarp();

        // ============================ layer 0 ============================
        u64 cz[4][4], an[4][2], hn[4][2];
#pragma unroll
        for (int s = 0; s < 4; s++) {
#pragma unroll
            for (int j = 0; j < 4; j++) cz[s][j] = pk0(sb[((j >> 1) << 6) + lane + ((j & 1) << 5)]);
            an[s][0] = pk0(sb[128 + lane]); an[s][1] = pk0(sb[160 + lane]);
            hn[s][0] = pk0(sb[192 + lane]); hn[s][1] = pk0(sb[224 + lane]);
        }
        // x part
#pragma unroll
        for (int k2 = 0; k2 < DIN / 2; k2++) {
            const float* wb = wih0p + k2 * 384;
            u64 wv[6];
#pragma unroll
            for (int j = 0; j < 6; j++) wv[j] = lds64(wb + wo[j]);
#pragma unroll
            for (int s = 0; s < 4; s++) {
                u64 x2 = lds64(sxw + s * DIN + 2 * k2);
                cz[s][0] = ffma2(wv[0], x2, cz[s][0]);
                cz[s][1] = ffma2(wv[1], x2, cz[s][1]);
                cz[s][2] = ffma2(wv[2], x2, cz[s][2]);
                cz[s][3] = ffma2(wv[3], x2, cz[s][3]);
                an[s][0] = ffma2(wv[4], x2, an[s][0]);
                an[s][1] = ffma2(wv[5], x2, an[s][1]);
            }
        }
        // h part
#pragma unroll 2
        for (int k2 = 0; k2 < 32; k2++) {
            const float* wb = whh0p + k2 * 384;
            u64 wv[6];
#pragma unroll
            for (int j = 0; j < 6; j++) wv[j] = lds64(wb + wo[j]);
#pragma unroll
            for (int s = 0; s < 4; s++) {
                u64 h2 = lds64(sh0 + (sl + s) * 64 + 2 * k2);
                cz[s][0] = ffma2(wv[0], h2, cz[s][0]);
                cz[s][1] = ffma2(wv[1], h2, cz[s][1]);
                cz[s][2] = ffma2(wv[2], h2, cz[s][2]);
                cz[s][3] = ffma2(wv[3], h2, cz[s][3]);
                hn[s][0] = ffma2(wv[4], h2, hn[s][0]);
                hn[s][1] = ffma2(wv[5], h2, hn[s][1]);
            }
        }
        __syncwarp();
#pragma unroll
        for (int s = 0; s < 4; s++)
#pragma unroll
            for (int u = 0; u < 2; u++) {
                float r = fsig(red2(cz[s][u]));
                float z = fsig(red2(cz[s][2 + u]));
                float n = ftanh(fmaf(r, red2(hn[s][u]), red2(an[s][u])));
                int hi = (sl + s) * 64 + lane + (u << 5);
                float hold = sh0[hi];
                sh0[hi] = (1.f - z) * n + z * hold;
            }
        __syncwarp();

        // ============================ layer 1 ============================
#pragma unroll
        for (int s = 0; s < 4; s++) {
#pragma unroll
            for (int j = 0; j < 4; j++) cz[s][j] = pk0(sb[256 + ((j >> 1) << 6) + lane + ((j & 1) << 5)]);
            an[s][0] = pk0(sb[384 + lane]); an[s][1] = pk0(sb[416 + lane]);
            hn[s][0] = pk0(sb[448 + lane]); hn[s][1] = pk0(sb[480 + lane]);
        }
#pragma unroll 1
        for (int k2 = 0; k2 < 32; k2++) {
            {
                const float* wb = wih1p + k2 * 384;
                u64 wv[6];
#pragma unroll
                for (int j = 0; j < 6; j++) wv[j] = lds64(wb + wo[j]);
#pragma unroll
                for (int s = 0; s < 4; s++) {
                    u64 x2 = lds64(sh0 + (sl + s) * 64 + 2 * k2);
                    cz[s][0] = ffma2(wv[0], x2, cz[s][0]);
                    cz[s][1] = ffma2(wv[1], x2, cz[s][1]);
                    cz[s][2] = ffma2(wv[2], x2, cz[s][2]);
                    cz[s][3] = ffma2(wv[3], x2, cz[s][3]);
                    an[s][0] = ffma2(wv[4], x2, an[s][0]);
                    an[s][1] = ffma2(wv[5], x2, an[s][1]);
                }
            }
            {
                const float* wb = whh1p + k2 * 384;
                u64 wv[6];
#pragma unroll
                for (int j = 0; j < 6; j++) wv[j] = lds64(wb + wo[j]);
#pragma unroll
                for (int s = 0; s < 4; s++) {
                    u64 h2 = lds64(sh1 + (sl + s) * 64 + 2 * k2);
                    cz[s][0] = ffma2(wv[0], h2, cz[s][0]);
                    cz[s][1] = ffma2(wv[1], h2, cz[s][1]);
                    cz[s][2] = ffma2(wv[2], h2, cz[s][2]);
                    cz[s][3] = ffma2(wv[3], h2, cz[s][3]);
                    hn[s][0] = ffma2(wv[4], h2, hn[s][0]);
                    hn[s][1] = ffma2(wv[5], h2, hn[s][1]);
                }
            }
        }
        __syncwarp();
#pragma unroll
        for (int s = 0; s < 4; s++)
#pragma unroll
            for (int u = 0; u < 2; u++) {
                float r = fsig(red2(cz[s][u]));
                float z = fsig(red2(cz[s][2 + u]));
                float n = ftanh(fmaf(r, red2(hn[s][u]), red2(an[s][u])));
                int hi = (sl + s) * 64 + lane + (u << 5);
                float hold = sh1[hi];
                float hnew = (1.f - z) * n + z * hold;
                sh1[hi] = hnew;
                if (STORE_ALL) OUT[((long long)(sg + s) * T + t) * 64 + lane + (u << 5)] = hnew;
            }
        __syncwarp();
    }
    if (!STORE_ALL) {
#pragma unroll
        for (int s = 0; s < 4; s++)
#pragma unroll
            for (int u = 0; u < 2; u++)
                OUT[(long long)(sg + s) * 64 + lane + (u << 5)] = sh1[(sl + s) * 64 + lane + (u << 5)];
    }
}

// =========================================================================
// xp = h @ trans_W.T + trans_b ; s_dst = xp @ a[:64] ; s_src = xp @ a[64:]
// =========================================================================
__global__ void trans_score_kernel(const float* __restrict__ H,
    const float* __restrict__ W, const float* __restrict__ b,
    const float* __restrict__ a, float* __restrict__ ssrc,
    float* __restrict__ sdst, int Nrows)
{
    __shared__ float sW[4096], sbv[64], sad[64], sas[64];
    for (int i = threadIdx.x; i < 4096; i += blockDim.x) sW[i] = W[i];
    for (int i = threadIdx.x; i < 64; i += blockDim.x) { sbv[i] = b[i]; sad[i] = a[i]; sas[i] = a[64 + i]; }
    __syncthreads();
    for (int row = blockIdx.x * blockDim.x + threadIdx.x; row < Nrows; row += gridDim.x * blockDim.x) {
        float h[64];
        const float4* hp = (const float4*)(H + (long long)row * 64);
#pragma unroll
        for (int q = 0; q < 16; q++) { float4 v = hp[q]; h[4*q] = v.x; h[4*q+1] = v.y; h[4*q+2] = v.z; h[4*q+3] = v.w; }
        float sd = 0.f, ss = 0.f;
#pragma unroll 4
        for (int o = 0; o < 64; o++) {
            float acc = sbv[o];
#pragma unroll
            for (int k = 0; k < 64; k++) acc = fmaf(h[k], sW[o * 64 + k], acc);
            sd = fmaf(acc, sad[o], sd);
            ss = fmaf(acc, sas[o], ss);
        }
        sdst[row] = sd; ssrc[row] = ss;
    }
}

// =========================================================================
// Dense per-group GAT: out[i] = softmax_j(lrelu(ssrc[i]+sdst[j])) @ h + h[i]
// =========================================================================
__global__ void gat_att_kernel(const float* __restrict__ Hin,
    const float* __restrict__ ssrc, const float* __restrict__ sdst,
    float* __restrict__ Hout)
{
    __shared__ float sd[512];
    __shared__ float se[8][512];
    const int g = blockIdx.x >> 3, chunk = blockIdx.x & 7;
    for (int i = threadIdx.x; i < 512; i += blockDim.x) sd[i] = sdst[g * 512 + i];
    __syncthreads();
    const int w = threadIdx.x >> 5, lane = threadIdx.x & 31;
    const float* Hg = Hin + (long long)g * 512 * 64;
    for (int rr = 0; rr < 8; ++rr) {
        const int i = chunk * 64 + w * 8 + rr;
        const float si = ssrc[g * 512 + i];
        float m = -1e30f, sc[16];
#pragma unroll
        for (int jj = 0; jj < 16; jj++) {
            float v = lrelu(si + sd[lane + (jj << 5)]);
            sc[jj] = v; m = fmaxf(m, v);
        }
#pragma unroll
        for (int off = 16; off; off >>= 1) m = fmaxf(m, __shfl_xor_sync(~0u, m, off));
        float ssum = 0.f;
#pragma unroll
        for (int jj = 0; jj < 16; jj++) {
            float e = __expf(sc[jj] - m);
            se[w][lane + (jj << 5)] = e; ssum += e;
        }
#pragma unroll
        for (int off = 16; off; off >>= 1) ssum += __shfl_xor_sync(~0u, ssum, off);
        __syncwarp();
        float2 acc = make_float2(0.f, 0.f);
        const int c = lane << 1;
#pragma unroll 4
        for (int j = 0; j < 512; j++) {
            float e = se[w][j];
            float2 hv = *(const float2*)(Hg + j * 64 + c);
            acc.x = fmaf(e, hv.x, acc.x);
            acc.y = fmaf(e, hv.y, acc.y);
        }
        float inv = __fdividef(1.f, ssum);
        float2 hi = *(const float2*)(Hg + i * 64 + c);
        float2 res; res.x = fmaf(acc.x, inv, hi.x); res.y = fmaf(acc.y, inv, hi.y);
        *(float2*)(Hout + ((long long)g * 512 + i) * 64 + c) = res;
        __syncwarp();
    }
}

// ============================ fc: 64x64 linear ===========================
__global__ void fc_kernel(const float* __restrict__ IN, const float* __restrict__ W,
                          const float* __restrict__ b, float* __restrict__ O, int Nrows)
{
    __shared__ float sW[4096], sb2[64];
    for (int i = threadIdx.x; i < 4096; i += blockDim.x) sW[i] = W[i];
    for (int i = threadIdx.x; i < 64; i += blockDim.x) sb2[i] = b[i];
    __syncthreads();
    for (int row = blockIdx.x * blockDim.x + threadIdx.x; row < Nrows; row += gridDim.x * blockDim.x) {
        float h[64];
        const float4* hp = (const float4*)(IN + (long long)row * 64);
#pragma unroll
        for (int q = 0; q < 16; q++) { float4 v = hp[q]; h[4*q] = v.x; h[4*q+1] = v.y; h[4*q+2] = v.z; h[4*q+3] = v.w; }
        float* op = O + (long long)row * 64;
#pragma unroll 2
        for (int o = 0; o < 64; o++) {
            float acc = sb2[o];
#pragma unroll
            for (int k = 0; k < 64; k++) acc = fmaf(h[k], sW[o * 64 + k], acc);
            op[o] = acc;
        }
    }
}

// ============= z = tanh(permute(hfc) @ al_in_W.T + al_in_b) ==============
__global__ void z_kernel(const float* __restrict__ Hfc, const float* __restrict__ W,
                         const float* __restrict__ b, float* __restrict__ Z)
{
    __shared__ float sW[4096], sb2[64];
    for (int i = threadIdx.x; i < 4096; i += blockDim.x) sW[i] = W[i];
    for (int i = threadIdx.x; i < 64; i += blockDim.x) sb2[i] = b[i];
    __syncthreads();
    int r = blockIdx.x * blockDim.x + threadIdx.x;
    if (r >= 512 * 20) return;
    int i = r / 20, k = r - i * 20;
    const float* hp = Hfc + (long long)(k * 512 + i) * 64;
    float h[64];
#pragma unroll
    for (int q = 0; q < 16; q++) { float4 v = ((const float4*)hp)[q]; h[4*q] = v.x; h[4*q+1] = v.y; h[4*q+2] = v.z; h[4*q+3] = v.w; }
    float* op = Z + (long long)r * 64;
#pragma unroll 2
    for (int o = 0; o < 64; o++) {
        float acc = sb2[o];
#pragma unroll
        for (int kk = 0; kk < 64; kk++) acc = fmaf(h[kk], sW[o * 64 + kk], acc);
        op[o] = ftanh(acc);
    }
}

// ======================= ALSTM attention head ============================
__global__ void alstm_head_kernel(const float* __restrict__ R,
    const float* __restrict__ W1, const float* __restrict__ b1,
    const float* __restrict__ W2, const float* __restrict__ Wout,
    const float* __restrict__ bout, float* __restrict__ outv)
{
    __shared__ float sW1t[64 * 32], sb1[32], sW2[32], sWo[128];
    __shared__ float sr[8][64], ssk[8][20];
    for (int i = threadIdx.x; i < 2048; i += blockDim.x) { int d = i >> 5, o = i & 31; sW1t[i] = W1[o * 64 + d]; }
    if (threadIdx.x < 32) { sb1[threadIdx.x] = b1[threadIdx.x]; sW2[threadIdx.x] = W2[threadIdx.x]; }
    for (int i = threadIdx.x; i < 128; i += blockDim.x) sWo[i] = Wout[i];
    __syncthreads();
    const int w = threadIdx.x >> 5, lane = threadIdx.x & 31;
    const int i = blockIdx.x * 8 + w;
    const float* Ri = R + (long long)i * 20 * 64;
    for (int k = 0; k < 20; k++) {
        sr[w][lane] = Ri[k * 64 + lane];
        sr[w][lane + 32] = Ri[k * 64 + lane + 32];
        __syncwarp();
        float acc = sb1[lane];
#pragma unroll
        for (int d = 0; d < 64; d++) acc = fmaf(sr[w][d], sW1t[(d << 5) + lane], acc);
        float p = ftanh(acc) * sW2[lane];
#pragma unroll
        for (int off = 16; off; off >>= 1) p += __shfl_xor_sync(~0u, p, off);
        if (lane == 0) ssk[w][k] = p;
        __syncwarp();
    }
    float m = -1e30f;
    for (int k = 0; k < 20; k++) m = fmaxf(m, ssk[w][k]);
    float ssum = 0.f;
    for (int k = 0; k < 20; k++) ssum += __expf(ssk[w][k] - m);
    float inv = __fdividef(1.f, ssum);
    float accf = 0.f;
    for (int k = 0; k < 20; k++) {
        float ak = __expf(ssk[w][k] - m) * inv;
        float r1 = Ri[k * 64 + lane], r2 = Ri[k * 64 + lane + 32];
        accf = fmaf(ak * r1, sWo[64 + lane], accf);
        accf = fmaf(ak * r2, sWo[96 + lane], accf);
    }
    {
        float r1 = Ri[19 * 64 + lane], r2 = Ri[19 * 64 + lane + 32];
        accf = fmaf(r1, sWo[lane], accf);
        accf = fmaf(r2, sWo[32 + lane], accf);
    }
#pragma unroll
    for (int off = 16; off; off >>= 1) accf += __shfl_xor_sync(~0u, accf, off);
    if (lane == 0) outv[i] = accf + bout[0];
}

// ============ pred = lrelu(hfc[group 19]) @ fco_W.T + fco_b ==============
__global__ void pred_kernel(const float* __restrict__ Hfc, const float* __restrict__ fcoW,
                            const float* __restrict__ fcob, float* __restrict__ outv)
{
    __shared__ float sw[64];
    if (threadIdx.x < 64) sw[threadIdx.x] = fcoW[threadIdx.x];
    __syncthreads();
    int i = blockIdx.x * blockDim.x + threadIdx.x;
    if (i < 512) {
        const float* hp = Hfc + (long long)(19 * 512 + i) * 64;
        float s = fcob[0];
#pragma unroll 8
        for (int c = 0; c < 64; c++) { float v = hp[c]; v = v > 0.f ? v : 0.01f * v; s = fmaf(v, sw[c], s); }
        outv[512 + i] = s;
    }
}

// =========================================================================
extern "C" void kernel_launch(void* const* d_in, const int* in_sizes, int n_in,
                              void* d_out, int out_size)
{
    const float* x        = (const float*)d_in[0];
    const float* rWih0    = (const float*)d_in[1];
    const float* rWhh0    = (const float*)d_in[2];
    const float* rbih0    = (const float*)d_in[3];
    const float* rbhh0    = (const float*)d_in[4];
    const float* rWih1    = (const float*)d_in[5];
    const float* rWhh1    = (const float*)d_in[6];
    const float* rbih1    = (const float*)d_in[7];
    const float* rbhh1    = (const float*)d_in[8];
    const float* trans_W  = (const float*)d_in[9];
    const float* trans_b  = (const float*)d_in[10];
    const float* a_vec    = (const float*)d_in[11];
    const float* fc_W     = (const float*)d_in[12];
    const float* fc_b     = (const float*)d_in[13];
    const float* fco_W    = (const float*)d_in[14];
    const float* fco_b    = (const float*)d_in[15];
    const float* al_in_W  = (const float*)d_in[16];
    const float* al_in_b  = (const float*)d_in[17];
    const float* aWih0    = (const float*)d_in[18];
    const float* aWhh0    = (const float*)d_in[19];
    const float* abih0    = (const float*)d_in[20];
    const float* abhh0    = (const float*)d_in[21];
    const float* aWih1    = (const float*)d_in[22];
    const float* aWhh1    = (const float*)d_in[23];
    const float* abih1    = (const float*)d_in[24];
    const float* abhh1    = (const float*)d_in[25];
    const float* att1_W   = (const float*)d_in[26];
    const float* att1_b   = (const float*)d_in[27];
    const float* att2_W   = (const float*)d_in[28];
    const float* out_W    = (const float*)d_in[29];
    const float* out_b    = (const float*)d_in[30];
    float* out = (float*)d_out;

    float *hlast, *ssrc, *sdst, *hatt, *hfc, *zb, *rb;
    cudaGetSymbolAddress((void**)&hlast, g_hlast);
    cudaGetSymbolAddress((void**)&ssrc,  g_ssrc);
    cudaGetSymbolAddress((void**)&sdst,  g_sdst);
    cudaGetSymbolAddress((void**)&hatt,  g_hatt);
    cudaGetSymbolAddress((void**)&hfc,   g_hfc);
    cudaGetSymbolAddress((void**)&zb,    g_z);
    cudaGetSymbolAddress((void**)&rb,    g_r);

    // smem floats: DIN*192 + 3*12288 + 512 + 2*SPB*64 + WARPS*4*DIN
    const int ENC_SMEM = (6 * 192 + 3 * 12288 + 512 + 2 * 72 * 64 + 18 * 4 * 6) * 4;   // 192704
    const int AL_SMEM  = (64 * 192 + 3 * 12288 + 512 + 2 * 16 * 64 + 4 * 4 * 64) * 4;  // 210944
    cudaFuncSetAttribute((const void*)gru2p_kernel<6, false>,
                         cudaFuncAttributeMaxDynamicSharedMemorySize, ENC_SMEM);
    cudaFuncSetAttribute((const void*)gru2p_kernel<64, true>,
                         cudaFuncAttributeMaxDynamicSharedMemorySize, AL_SMEM);

    // 1) encoder: 2-layer GRU, N=10240, T=60 -> hlast (143 blocks = 1 wave)
    gru2p_kernel<6, false><<<143, 576, ENC_SMEM>>>(
        x, rWih0, rWhh0, rbih0, rbhh0, rWih1, rWhh1, rbih1, rbhh1, hlast, 10240, 60);

    // 2) trans projection + rank-1 scores
    trans_score_kernel<<<40, 256>>>(hlast, trans_W, trans_b, a_vec, ssrc, sdst, 10240);

    // 3) per-group dense attention + residual
    gat_att_kernel<<<160, 256>>>(hlast, ssrc, sdst, hatt);

    // 4) fc
    fc_kernel<<<40, 256>>>(hatt, fc_W, fc_b, hfc, 10240);

    // 5) z = tanh(permuted hfc @ al_in_W.T + b)
    z_kernel<<<40, 256>>>(hfc, al_in_W, al_in_b, zb);

    // 6) ALSTM 2-layer GRU over K=20, batch 512, store all timesteps
    gru2p_kernel<64, true><<<32, 128, AL_SMEM>>>(
        zb, aWih0, aWhh0, abih0, abhh0, aWih1, aWhh1, abih1, abhh1, rb, 512, 20);

    // 7) ALSTM attention head -> alstm_out (out[0:512])
    alstm_head_kernel<<<64, 256>>>(rb, att1_W, att1_b, att2_W, out_W, out_b, out);

    // 8) pred head -> out[512:1024]
    pred_kernel<<<2, 256>>>(hfc, fco_W, fco_b, out);
}